// round 15
// baseline (speedup 1.0000x reference)
#include <cuda_runtime.h>
#include <cuda_bf16.h>
#include <math.h>

// Problem constants
#define BB   128
#define HH   512
#define DD   64
#define SS   512
#define LBL  96
#define PRD  192
#define DECL (LBL + PRD)     // 288
#define TTF  (SS + LBL)      // 608 teacher-forced steps

#define NTHR 256             // threads per CTA (8 warps)
#define NCTA 128             // CTAs
#define AST  36              // A-chunk row stride in words (36 % 32 == 4; 144B -> LDSM conflict-free)
#define NST  3               // A-ring stages
#define ABUF (BB*AST)        // words per A buffer
#define NC0  9               // layer0 chunks: (64 + 512) / 64
#define NC1  16              // layer1 chunks: (512 + 512) / 64
#define W0S  292             // layer0 weight row stride words (1168B -> LDSM conflict-free)
#define W1S  516             // layer1 weight row stride words (2064B -> conflict-free)

// Split-weight segment offsets (elements)
#define SZ0 (4*HH*DD)
#define SZH (4*HH*HH)
#define O_EW0I 0
#define O_EW0H (O_EW0I + SZ0)
#define O_EW1I (O_EW0H + SZH)
#define O_EW1H (O_EW1I + SZH)
#define O_DW0I (O_EW1H + SZH)
#define O_DW0H (O_DW0I + SZ0)
#define O_DW1I (O_DW0H + SZH)
#define O_DW1H (O_DW1I + SZH)
#define WTOT   (O_DW1H + SZH)

// Persistent device state (allocation-free scratch)
__device__ __align__(16) __nv_bfloat16 g_whi[WTOT];
__device__ __align__(16) __nv_bfloat16 g_wlo[WTOT];
__device__ __align__(16) __nv_bfloat16 g_xeh[BB*SS*DD];    // x_enc hi
__device__ __align__(16) __nv_bfloat16 g_xel[BB*SS*DD];    // x_enc lo
__device__ __align__(16) __nv_bfloat16 g_xdh[BB*DECL*DD];  // x_dec hi
__device__ __align__(16) __nv_bfloat16 g_xdl[BB*DECL*DD];  // x_dec lo
__device__ __align__(16) __nv_bfloat16 g_hh[2][2][BB*HH];  // h hi [layer][pp]
__device__ __align__(16) __nv_bfloat16 g_hl[2][2][BB*HH];  // h lo
__device__ __align__(16) float         g_h1f[BB*HH];       // layer1 h fp32 (proj)
__device__ __align__(16) float         g_c[2][BB*HH];      // cell state (CTA-private)
__device__ __align__(16) __nv_bfloat16 g_ph[BB*DD];        // pred hi (AR feedback)
__device__ __align__(16) __nv_bfloat16 g_pl[BB*DD];        // pred lo
__device__ unsigned g_bar_count;
__device__ volatile unsigned g_bar_sense;

struct Smem {
    unsigned w0hi[16*W0S], w0lo[16*W0S];        // layer0 weights (ih|hh fused K)
    unsigned w1hi[16*W1S], w1lo[16*W1S];        // layer1 weights
    unsigned ahi[NST][ABUF], alo[NST][ABUF];    // 3-stage A ring
};                                              // ~214 KB

// ---------------------------------------------------------------------------
// Prep: split fp32 -> (hi, lo) bf16 for weights and inputs. One-off.
__global__ void prep_split(const float* e0i, const float* e0h,
                           const float* e1i, const float* e1h,
                           const float* d0i, const float* d0h,
                           const float* d1i, const float* d1h,
                           const float* xe, const float* xd)
{
    const float* src; __nv_bfloat16 *dh, *dl; int n;
    switch (blockIdx.y) {
        case 0: src = e0i; dh = g_whi + O_EW0I; dl = g_wlo + O_EW0I; n = SZ0; break;
        case 1: src = e0h; dh = g_whi + O_EW0H; dl = g_wlo + O_EW0H; n = SZH; break;
        case 2: src = e1i; dh = g_whi + O_EW1I; dl = g_wlo + O_EW1I; n = SZH; break;
        case 3: src = e1h; dh = g_whi + O_EW1H; dl = g_wlo + O_EW1H; n = SZH; break;
        case 4: src = d0i; dh = g_whi + O_DW0I; dl = g_wlo + O_DW0I; n = SZ0; break;
        case 5: src = d0h; dh = g_whi + O_DW0H; dl = g_wlo + O_DW0H; n = SZH; break;
        case 6: src = d1i; dh = g_whi + O_DW1I; dl = g_wlo + O_DW1I; n = SZH; break;
        case 7: src = d1h; dh = g_whi + O_DW1H; dl = g_wlo + O_DW1H; n = SZH; break;
        case 8: src = xe;  dh = g_xeh; dl = g_xel; n = BB*SS*DD;   break;
        default: src = xd; dh = g_xdh; dl = g_xdl; n = BB*DECL*DD; break;
    }
    for (int i = blockIdx.x * blockDim.x + threadIdx.x; i < n;
         i += gridDim.x * blockDim.x) {
        float v = src[i];
        __nv_bfloat16 h = __float2bfloat16(v);
        dh[i] = h;
        dl[i] = __float2bfloat16(v - __bfloat162float(h));
    }
}

// ---------------------------------------------------------------------------
__device__ __forceinline__ void grid_sync(unsigned* s_sense) {
    __syncthreads();
    if (threadIdx.x == 0) {
        unsigned want = *s_sense ^ 1u;
        *s_sense = want;
        __threadfence();
        if (atomicAdd(&g_bar_count, 1u) == NCTA - 1u) {
            atomicExch(&g_bar_count, 0u);
            __threadfence();
            g_bar_sense = want;
        } else {
            while (g_bar_sense != want) __nanosleep(32);
        }
        __threadfence();
    }
    __syncthreads();
}

__device__ __forceinline__ float sigf(float v) { return 1.0f / (1.0f + __expf(-v)); }
__device__ __forceinline__ float tanhfast(float v) { return 2.0f / (1.0f + __expf(-2.0f * v)) - 1.0f; }

__device__ __forceinline__ void mma16816(float* d, const unsigned* a,
                                         unsigned b0, unsigned b1) {
    asm volatile(
        "mma.sync.aligned.m16n8k16.row.col.f32.bf16.bf16.f32 "
        "{%0,%1,%2,%3}, {%4,%5,%6,%7}, {%8,%9}, {%0,%1,%2,%3};"
        : "+f"(d[0]), "+f"(d[1]), "+f"(d[2]), "+f"(d[3])
        : "r"(a[0]), "r"(a[1]), "r"(a[2]), "r"(a[3]), "r"(b0), "r"(b1));
}

__device__ __forceinline__ void ldsm4(unsigned* r, unsigned addr) {
    asm volatile("ldmatrix.sync.aligned.m8n8.x4.shared.b16 {%0,%1,%2,%3}, [%4];"
        : "=r"(r[0]), "=r"(r[1]), "=r"(r[2]), "=r"(r[3]) : "r"(addr));
}

__device__ __forceinline__ void st_bf16_cg(__nv_bfloat16* p, __nv_bfloat16 v) {
    asm volatile("st.global.cg.u16 [%0], %1;"
                 :: "l"(p), "h"(__bfloat16_as_ushort(v)) : "memory");
}

__device__ __forceinline__ void cp_async16(void* s, const void* g) {
    unsigned sa = (unsigned)__cvta_generic_to_shared(s);
    asm volatile("cp.async.cg.shared.global [%0], [%1], 16;"
                 :: "r"(sa), "l"(g) : "memory");
}
#define CP_COMMIT() asm volatile("cp.async.commit_group;" ::: "memory")
#define CP_WAIT1()  asm volatile("cp.async.wait_group 1;" ::: "memory")
#define CP_WAIT0()  asm volatile("cp.async.wait_group 0;" ::: "memory")

// ---------------------------------------------------------------------------
// Load this CTA's 16-gate-row weight slice (ih|hh fused along K) into SMEM.
__device__ void load_weights(unsigned* whi, unsigned* wlo, int WS, int xK,
                             const unsigned* ihh, const unsigned* ihl,
                             const unsigned* hhh, const unsigned* hhl,
                             int hb, int tid)
{
    const int xw = xK >> 1;                 // ih words per row
    const int twords = (xK + HH) >> 1;      // total words per row
    for (int idx = tid; idx < 16 * twords; idx += NTHR) {
        int c = idx / twords;
        int w = idx - c * twords;
        int j = (c & 3) * HH + hb + (c >> 2);
        unsigned vh, vl;
        if (w < xw) { vh = ihh[j * xw + w];          vl = ihl[j * xw + w]; }
        else        { vh = hhh[j * 256 + (w - xw)];  vl = hhl[j * 256 + (w - xw)]; }
        whi[c * WS + w] = vh;
        wlo[c * WS + w] = vl;
    }
    __syncthreads();
}

// ---------------------------------------------------------------------------
// One LSTM cell slice: split-bf16 MMA, persistent SMEM weights,
// 3-stage cp.async ring (one syncthreads per chunk), ldmatrix fragment loads.
__device__ __noinline__ void lstm_slice(Smem* sm,
    const __nv_bfloat16* a0h, const __nv_bfloat16* a0l, int a0str, int n0,
    const __nv_bfloat16* hph, const __nv_bfloat16* hpl,
    const unsigned* whi, const unsigned* wlo, int WS, int NC,
    const float* __restrict__ bih, const float* __restrict__ bhh,
    __nv_bfloat16* hnh, __nv_bfloat16* hnl, float* hnf,
    float* c_st, int hb)
{
    const int tid  = threadIdx.x;
    const int w    = tid >> 5;
    const int lane = tid & 31;
    const int tq   = lane >> 2;   // 0..7
    const int tp   = lane & 3;    // 0..3

    auto stage = [&](int c, int buf) {
        const __nv_bfloat16 *sh, *sl; int k0, str;
        if (c < n0) { sh = a0h; sl = a0l; k0 = c * 64;        str = a0str; }
        else        { sh = hph; sl = hpl; k0 = (c - n0) * 64; str = HH;   }
        unsigned* dh = sm->ahi[buf];
        unsigned* dl = sm->alo[buf];
#pragma unroll
        for (int i = 0; i < 4; ++i) {
            int o   = tid + i * NTHR;
            int row = o >> 3, seg = o & 7;
            size_t ge = (size_t)row * str + k0 + seg * 8;
            int sw = row * AST + seg * 4;
            cp_async16(dh + sw, sh + ge);
            cp_async16(dl + sw, sl + ge);
        }
    };

    float d0[4] = {0.f, 0.f, 0.f, 0.f};
    float d1[4] = {0.f, 0.f, 0.f, 0.f};

    // ldmatrix lane addressing.
    // A x4: m0 rows0-7/klo, m1 rows8-15/klo, m2 rows0-7/khi, m3 rows8-15/khi
    const int arow  = w * 16 + (lane & 7) + ((lane >> 3) & 1) * 8;
    const unsigned abyte = (unsigned)(arow * AST + ((lane >> 4) & 1) * 4) * 4u;
    const unsigned aHbase = (unsigned)__cvta_generic_to_shared(sm->ahi) + abyte;
    const unsigned aLbase = (unsigned)__cvta_generic_to_shared(sm->alo) + abyte;
    // B x4: m0 n0-7/klo, m1 n0-7/khi, m2 n8-15/klo, m3 n8-15/khi
    const int brow  = (lane & 7) + ((lane >> 4) & 1) * 8;
    const unsigned bbyte = (unsigned)(brow * WS + ((lane >> 3) & 1) * 4) * 4u;
    const unsigned bHbase = (unsigned)__cvta_generic_to_shared(whi) + bbyte;
    const unsigned bLbase = (unsigned)__cvta_generic_to_shared(wlo) + bbyte;

    __syncthreads();               // previous slice fully done with A ring
    stage(0, 0); CP_COMMIT();
    stage(1, 1); CP_COMMIT();

#pragma unroll 1
    for (int c = 0; c < NC; ++c) {
        if (c + 1 < NC) CP_WAIT1(); else CP_WAIT0();
        __syncthreads();           // stage c visible to all; buf (c+2)%3 free
        if (c + 2 < NC) { stage(c + 2, (c + 2) % 3); CP_COMMIT(); }

        const unsigned aH = aHbase + (unsigned)((c % 3) * (ABUF * 4));
        const unsigned aL = aLbase + (unsigned)((c % 3) * (ABUF * 4));
        const unsigned bH = bHbase + (unsigned)(c * 128);
        const unsigned bL = bLbase + (unsigned)(c * 128);

#pragma unroll
        for (int s = 0; s < 4; ++s) {
            unsigned ah[4], al[4], bh[4], bl[4];
            ldsm4(ah, aH + s * 32);
            ldsm4(al, aL + s * 32);
            ldsm4(bh, bH + s * 32);
            ldsm4(bl, bL + s * 32);
            mma16816(d0, ah, bh[0], bh[1]);
            mma16816(d0, ah, bl[0], bl[1]);
            mma16816(d0, al, bh[0], bh[1]);
            mma16816(d1, ah, bh[2], bh[3]);
            mma16816(d1, ah, bl[2], bl[3]);
            mma16816(d1, al, bh[2], bh[3]);
        }
    }

    // Epilogue: bias + i/f <-> g/o exchange (lane t <-> t^1) + cell update.
#pragma unroll
    for (int nh = 0; nh < 2; ++nh) {
        float* d = nh ? d1 : d0;
        int cA = nh * 8 + 2 * tp;
        int cB = cA + 1;
        int jA = (cA & 3) * HH + hb + (cA >> 2);
        int jB = (cB & 3) * HH + hb + (cB >> 2);
        float bA = bih[jA] + bhh[jA];
        float bB = bih[jB] + bhh[jB];
        float v0 = d[0] + bA, v1 = d[1] + bB;
        float v2 = d[2] + bA, v3 = d[3] + bB;
        float p0 = __shfl_xor_sync(0xffffffffu, v0, 1);
        float p1 = __shfl_xor_sync(0xffffffffu, v1, 1);
        float p2 = __shfl_xor_sync(0xffffffffu, v2, 1);
        float p3 = __shfl_xor_sync(0xffffffffu, v3, 1);
        if ((tp & 1) == 0) {       // even tp holds (i,f); partner holds (g,o)
            int u  = cA >> 2;
            int m0 = w * 16 + tq;
#pragma unroll
            for (int rr = 0; rr < 2; ++rr) {
                float iv = sigf(rr ? v2 : v0);
                float fv = sigf(rr ? v3 : v1);
                float gv = tanhfast(rr ? p2 : p0);
                float ov = sigf(rr ? p3 : p1);
                int gidx = (m0 + rr * 8) * HH + hb + u;
                float cv = fv * c_st[gidx] + iv * gv;
                c_st[gidx] = cv;
                float hv = ov * tanhfast(cv);
                __nv_bfloat16 hbf = __float2bfloat16(hv);
                st_bf16_cg(&hnh[gidx], hbf);
                st_bf16_cg(&hnl[gidx], __float2bfloat16(hv - __bfloat162float(hbf)));
                if (hnf) __stcg(&hnf[gidx], hv);
            }
        }
    }
}

// ---------------------------------------------------------------------------
// Projection: CTA b computes pred[b, 0:64] = h1[b,:] @ W.T + bias (fp32).
__device__ __forceinline__ void proj_slice(
    const float* __restrict__ W, const float* __restrict__ bias,
    const float* __restrict__ h1, float* __restrict__ out_step)
{
    const int bI = blockIdx.x;
    const float* hrow = h1 + (size_t)bI * HH;
    const int w = threadIdx.x >> 5;
    const int l = threadIdx.x & 31;

#pragma unroll
    for (int p = 0; p < 8; ++p) {
        int dcol = p * 8 + w;
        const float* wr = W + (size_t)dcol * HH;
        float s = 0.0f;
#pragma unroll
        for (int m = 0; m < 4; ++m) {
            int k = m * 128 + 4 * l;
            float4 wv = *(const float4*)(wr + k);
            float4 hv = __ldcg((const float4*)(hrow + k));
            s = fmaf(wv.x, hv.x, s);
            s = fmaf(wv.y, hv.y, s);
            s = fmaf(wv.z, hv.z, s);
            s = fmaf(wv.w, hv.w, s);
        }
#pragma unroll
        for (int o = 16; o; o >>= 1) s += __shfl_xor_sync(0xffffffffu, s, o);
        if (l == 0) {
            float v = s + bias[dcol];
            out_step[(size_t)bI * (PRD * DD) + dcol] = v;
            __nv_bfloat16 hbf = __float2bfloat16(v);
            st_bf16_cg(&g_ph[bI * DD + dcol], hbf);
            st_bf16_cg(&g_pl[bI * DD + dcol], __float2bfloat16(v - __bfloat162float(hbf)));
        }
    }
}

// ---------------------------------------------------------------------------
__global__ void __launch_bounds__(NTHR, 1)
lstm_persistent(const float* ebih0, const float* ebhh0,
                const float* ebih1, const float* ebhh1,
                const float* dbih0, const float* dbhh0,
                const float* dbih1, const float* dbhh1,
                const float* projW, const float* projB,
                float* __restrict__ out)
{
    extern __shared__ char smem_raw[];
    Smem* sm = (Smem*)smem_raw;
    __shared__ unsigned s_sense;
    const int tid = threadIdx.x;
    const int hb  = blockIdx.x * 4;

    if (tid == 0) s_sense = g_bar_sense;

    const unsigned short z = 0;
    for (int i = blockIdx.x * NTHR + tid; i < BB * HH; i += NCTA * NTHR) {
        g_hh[0][0][i] = __ushort_as_bfloat16(z);
        g_hh[1][0][i] = __ushort_as_bfloat16(z);
        g_hl[0][0][i] = __ushort_as_bfloat16(z);
        g_hl[1][0][i] = __ushort_as_bfloat16(z);
        g_c[0][i] = 0.0f; g_c[1][i] = 0.0f;
    }
    grid_sync(&s_sense);

    int p0 = 0, p1 = 0;

    // ---- Teacher-forced region (pipelined: layer0(t) || layer1(t-1)) ----
    for (int t = 0; t <= TTF; ++t) {
        if (t == 0) {
            load_weights(sm->w0hi, sm->w0lo, W0S, DD,
                (const unsigned*)(g_whi + O_EW0I), (const unsigned*)(g_wlo + O_EW0I),
                (const unsigned*)(g_whi + O_EW0H), (const unsigned*)(g_wlo + O_EW0H), hb, tid);
            load_weights(sm->w1hi, sm->w1lo, W1S, HH,
                (const unsigned*)(g_whi + O_EW1I), (const unsigned*)(g_wlo + O_EW1I),
                (const unsigned*)(g_whi + O_EW1H), (const unsigned*)(g_wlo + O_EW1H), hb, tid);
        }
        if (t == SS)
            load_weights(sm->w0hi, sm->w0lo, W0S, DD,
                (const unsigned*)(g_whi + O_DW0I), (const unsigned*)(g_wlo + O_DW0I),
                (const unsigned*)(g_whi + O_DW0H), (const unsigned*)(g_wlo + O_DW0H), hb, tid);
        if (t == SS + 1)
            load_weights(sm->w1hi, sm->w1lo, W1S, HH,
                (const unsigned*)(g_whi + O_DW1I), (const unsigned*)(g_wlo + O_DW1I),
                (const unsigned*)(g_whi + O_DW1H), (const unsigned*)(g_wlo + O_DW1H), hb, tid);

        if (t < TTF) {
            bool enc = t < SS;
            const __nv_bfloat16* xh = enc ? g_xeh + (size_t)t * DD
                                          : g_xdh + (size_t)(t - SS) * DD;
            const __nv_bfloat16* xl = enc ? g_xel + (size_t)t * DD
                                          : g_xdl + (size_t)(t - SS) * DD;
            int xs = enc ? SS * DD : DECL * DD;
            lstm_slice(sm, xh, xl, xs, 1,
                       g_hh[0][p0], g_hl[0][p0],
                       sm->w0hi, sm->w0lo, W0S, NC0,
                       enc ? ebih0 : dbih0, enc ? ebhh0 : dbhh0,
                       g_hh[0][p0 ^ 1], g_hl[0][p0 ^ 1], nullptr,
                       g_c[0], hb);
        }
        if (t >= 1) {
            bool enc = (t - 1) < SS;
            lstm_slice(sm, g_hh[0][p0], g_hl[0][p0], HH, 8,
                       g_hh[1][p1], g_hl[1][p1],
                       sm->w1hi, sm->w1lo, W1S, NC1,
                       enc ? ebih1 : dbih1, enc ? ebhh1 : dbhh1,
                       g_hh[1][p1 ^ 1], g_hl[1][p1 ^ 1], g_h1f,
                       g_c[1], hb);
        }
        grid_sync(&s_sense);
        if (t < TTF) p0 ^= 1;
        if (t >= 1)  p1 ^= 1;
    }

    // pred0 -> out[:, 0, :] and AR feedback
    proj_slice(projW, projB, g_h1f, out);
    grid_sync(&s_sense);

    // ---- Autoregressive region ----
    for (int s = 1; s < PRD; ++s) {
        lstm_slice(sm, g_ph, g_pl, DD, 1,
                   g_hh[0][p0], g_hl[0][p0],
                   sm->w0hi, sm->w0lo, W0S, NC0,
                   dbih0, dbhh0,
                   g_hh[0][p0 ^ 1], g_hl[0][p0 ^ 1], nullptr,
                   g_c[0], hb);
        grid_sync(&s_sense);
        p0 ^= 1;

        lstm_slice(sm, g_hh[0][p0], g_hl[0][p0], HH, 8,
                   g_hh[1][p1], g_hl[1][p1],
                   sm->w1hi, sm->w1lo, W1S, NC1,
                   dbih1, dbhh1,
                   g_hh[1][p1 ^ 1], g_hl[1][p1 ^ 1], g_h1f,
                   g_c[1], hb);
        grid_sync(&s_sense);
        p1 ^= 1;

        proj_slice(projW, projB, g_h1f, out + (size_t)s * DD);
        grid_sync(&s_sense);
    }
}

// ---------------------------------------------------------------------------
extern "C" void kernel_launch(void* const* d_in, const int* in_sizes, int n_in,
                              void* d_out, int out_size)
{
    const float* x_enc = (const float*)d_in[0];
    const float* x_dec = (const float*)d_in[2];
    const float* eWih0 = (const float*)d_in[4];
    const float* eWhh0 = (const float*)d_in[5];
    const float* ebih0 = (const float*)d_in[6];
    const float* ebhh0 = (const float*)d_in[7];
    const float* eWih1 = (const float*)d_in[8];
    const float* eWhh1 = (const float*)d_in[9];
    const float* ebih1 = (const float*)d_in[10];
    const float* ebhh1 = (const float*)d_in[11];
    const float* dWih0 = (const float*)d_in[12];
    const float* dWhh0 = (const float*)d_in[13];
    const float* dbih0 = (const float*)d_in[14];
    const float* dbhh0 = (const float*)d_in[15];
    const float* dWih1 = (const float*)d_in[16];
    const float* dWhh1 = (const float*)d_in[17];
    const float* dbih1 = (const float*)d_in[18];
    const float* dbhh1 = (const float*)d_in[19];
    const float* projW = (const float*)d_in[20];
    const float* projB = (const float*)d_in[21];
    float* out = (float*)d_out;

    static int smem_set = 0;
    if (!smem_set) {
        cudaFuncSetAttribute(lstm_persistent,
                             cudaFuncAttributeMaxDynamicSharedMemorySize,
                             (int)sizeof(Smem));
        smem_set = 1;
    }

    // 1) split weights + inputs into bf16 hi/lo (one-off; 2-node graph)
    prep_split<<<dim3(512, 10), 256>>>(eWih0, eWhh0, eWih1, eWhh1,
                                       dWih0, dWhh0, dWih1, dWhh1,
                                       x_enc, x_dec);

    // 2) persistent seq2seq LSTM
    lstm_persistent<<<NCTA, NTHR, sizeof(Smem)>>>(
        ebih0, ebhh0, ebih1, ebhh1,
        dbih0, dbhh0, dbih1, dbhh1,
        projW, projB, out);
}